// round 5
// baseline (speedup 1.0000x reference)
#include <cuda_runtime.h>
#include <cstdint>

#define N_NODES 50000
#define N_EDGES 800000
#define IN_F 128
#define OUT_F 128
#define HEADS 4
#define HEAD_DIM 32

// ---------------- scratch (device globals; no allocation allowed) ----------------
__device__ float g_q[N_NODES * IN_F];
__device__ float g_k[N_NODES * IN_F];
__device__ float g_v[N_NODES * IN_F];
__device__ float g_den[N_NODES * HEADS];    // segment sum of exp(score)
__device__ float g_agg[N_NODES * OUT_F];    // UNNORMALIZED sum of exp(s)*v
__device__ float g_wot[OUT_F * OUT_F];      // wo transposed

// packed fp32x2 FMA (Blackwell FFMA2 — only reachable via PTX fma.rn.f32x2)
__device__ __forceinline__ unsigned long long ffma2(unsigned long long a,
                                                    unsigned long long b,
                                                    unsigned long long c) {
    unsigned long long d;
    asm("fma.rn.f32x2 %0, %1, %2, %3;" : "=l"(d) : "l"(a), "l"(b), "l"(c));
    return d;
}
__device__ __forceinline__ unsigned long long dup2(float w) {
    unsigned long long d;
    asm("mov.b64 %0, {%1, %1};" : "=l"(d) : "r"(__float_as_uint(w)));
    return d;
}
__device__ __forceinline__ float lo2(unsigned long long p) {
    unsigned int a, b;
    asm("mov.b64 {%0, %1}, %2;" : "=r"(a), "=r"(b) : "l"(p));
    return __uint_as_float(a);
}
__device__ __forceinline__ float hi2(unsigned long long p) {
    unsigned int a, b;
    asm("mov.b64 {%0, %1}, %2;" : "=r"(a), "=r"(b) : "l"(p));
    return __uint_as_float(b);
}

// ---------------- kernels ----------------

// zero agg/den + transpose wo (merged prep)
__global__ void prep_kernel(const float* __restrict__ wo) {
    int idx = blockIdx.x * blockDim.x + threadIdx.x;
    if (idx < N_NODES * OUT_F / 4)
        ((float4*)g_agg)[idx] = make_float4(0.f, 0.f, 0.f, 0.f);
    if (idx < N_NODES * HEADS)
        g_den[idx] = 0.f;
    if (idx < OUT_F * OUT_F) {
        int o = idx >> 7, f = idx & 127;
        g_wot[f * OUT_F + o] = wo[idx];
    }
}

// q,k,v projections with node-pair-packed FFMA2 + LDS.128 x loads.
// Block = 128 threads (thread t -> output column t = h*32+d), 32 nodes/block.
// smem layout: xs[f][n], stride 36 floats (144B = 9*16 -> 16B-aligned rows).
#define PROJ_NB 32
#define XS_STRIDE 36
__global__ void __launch_bounds__(128) proj_kernel(
    const float* __restrict__ x,
    const float* __restrict__ wq, const float* __restrict__ bq,
    const float* __restrict__ wk, const float* __restrict__ bk,
    const float* __restrict__ wv, const float* __restrict__ bv)
{
    __shared__ __align__(16) float xs[IN_F * XS_STRIDE];
    const int t = threadIdx.x;
    const int base = blockIdx.x * PROJ_NB;

    // stage x transposed: xs[f*36 + n] = x[base+n][f]
    for (int k = 0; k < 8; k++) {
        int i = t + k * 128;                 // 0..1023
        int n = i >> 5, c = i & 31;
        int node = base + n; if (node >= N_NODES) node = N_NODES - 1;
        float4 gx = ((const float4*)(x + (size_t)node * IN_F))[c];
        xs[(4 * c + 0) * XS_STRIDE + n] = gx.x;
        xs[(4 * c + 1) * XS_STRIDE + n] = gx.y;
        xs[(4 * c + 2) * XS_STRIDE + n] = gx.z;
        xs[(4 * c + 3) * XS_STRIDE + n] = gx.w;
    }
    __syncthreads();

    const int h = t >> 5, d = t & 31;
    const float* wqp = wq + h * IN_F * HEAD_DIM + d;
    const float* wkp = wk + h * IN_F * HEAD_DIM + d;
    const float* wvp = wv + h * IN_F * HEAD_DIM + d;

    unsigned long long aq[16], ak[16], av[16];
    const unsigned long long bq2 = dup2(bq[h * HEAD_DIM + d]);
    const unsigned long long bk2 = dup2(bk[h * HEAD_DIM + d]);
    const unsigned long long bv2 = dup2(bv[h * HEAD_DIM + d]);
#pragma unroll
    for (int j = 0; j < 16; j++) { aq[j] = bq2; ak[j] = bk2; av[j] = bv2; }

#pragma unroll 2
    for (int f = 0; f < IN_F; f++) {
        const unsigned long long wq2 = dup2(wqp[f * HEAD_DIM]);
        const unsigned long long wk2 = dup2(wkp[f * HEAD_DIM]);
        const unsigned long long wv2 = dup2(wvp[f * HEAD_DIM]);
        const ulonglong2* xp = (const ulonglong2*)(xs + f * XS_STRIDE);
#pragma unroll
        for (int j2 = 0; j2 < 8; j2++) {
            ulonglong2 xq = xp[j2];          // nodes 4j2 .. 4j2+3 (broadcast LDS.128)
            aq[2*j2]   = ffma2(xq.x, wq2, aq[2*j2]);
            ak[2*j2]   = ffma2(xq.x, wk2, ak[2*j2]);
            av[2*j2]   = ffma2(xq.x, wv2, av[2*j2]);
            aq[2*j2+1] = ffma2(xq.y, wq2, aq[2*j2+1]);
            ak[2*j2+1] = ffma2(xq.y, wk2, ak[2*j2+1]);
            av[2*j2+1] = ffma2(xq.y, wv2, av[2*j2+1]);
        }
    }

#pragma unroll
    for (int j = 0; j < 16; j++) {
        int n0 = base + 2 * j;
        if (n0 < N_NODES) {
            size_t r = (size_t)n0 * IN_F;
            g_q[r + t] = lo2(aq[j]); g_k[r + t] = lo2(ak[j]); g_v[r + t] = lo2(av[j]);
        }
        if (n0 + 1 < N_NODES) {
            size_t r = (size_t)(n0 + 1) * IN_F;
            g_q[r + t] = hi2(aq[j]); g_k[r + t] = hi2(ak[j]); g_v[r + t] = hi2(av[j]);
        }
    }
}

// FUSED edge pass, 2 edges per warp for MLP.
__global__ void __launch_bounds__(256) edge_kernel(const int* __restrict__ ei) {
    const int w = (blockIdx.x * blockDim.x + threadIdx.x) >> 5;
    const int lane = threadIdx.x & 31;
    const int e0 = w * 2;
    if (e0 >= N_EDGES) return;
    const int e1 = e0 + 1;

    const int s0 = __ldg(&ei[e0]),           s1 = __ldg(&ei[e1]);
    const int t0 = __ldg(&ei[N_EDGES + e0]), t1 = __ldg(&ei[N_EDGES + e1]);

    const float4 a0 = ((const float4*)(g_q + (size_t)t0 * IN_F))[lane];
    const float4 b0 = ((const float4*)(g_k + (size_t)s0 * IN_F))[lane];
    const float4 a1 = ((const float4*)(g_q + (size_t)t1 * IN_F))[lane];
    const float4 b1 = ((const float4*)(g_k + (size_t)s1 * IN_F))[lane];

    float p0 = a0.x * b0.x + a0.y * b0.y + a0.z * b0.z + a0.w * b0.w;
    float p1 = a1.x * b1.x + a1.y * b1.y + a1.z * b1.z + a1.w * b1.w;

    p0 += __shfl_xor_sync(0xffffffffu, p0, 4);
    p1 += __shfl_xor_sync(0xffffffffu, p1, 4);
    p0 += __shfl_xor_sync(0xffffffffu, p0, 2);
    p1 += __shfl_xor_sync(0xffffffffu, p1, 2);
    p0 += __shfl_xor_sync(0xffffffffu, p0, 1);
    p1 += __shfl_xor_sync(0xffffffffu, p1, 1);

    const float ex0 = __expf(p0);
    const float ex1 = __expf(p1);

    const float4 v0 = ((const float4*)(g_v + (size_t)s0 * IN_F))[lane];
    const float4 v1 = ((const float4*)(g_v + (size_t)s1 * IN_F))[lane];

    float* d0 = g_agg + (size_t)t0 * OUT_F + lane * 4;
    float* d1 = g_agg + (size_t)t1 * OUT_F + lane * 4;
    asm volatile("red.global.add.v4.f32 [%0], {%1, %2, %3, %4};"
                 :: "l"(d0), "f"(ex0 * v0.x), "f"(ex0 * v0.y),
                    "f"(ex0 * v0.z), "f"(ex0 * v0.w) : "memory");
    asm volatile("red.global.add.v4.f32 [%0], {%1, %2, %3, %4};"
                 :: "l"(d1), "f"(ex1 * v1.x), "f"(ex1 * v1.y),
                    "f"(ex1 * v1.z), "f"(ex1 * v1.w) : "memory");

    if ((lane & 7) == 0) atomicAdd(&g_den[t0 * HEADS + (lane >> 3)], ex0);
    if ((lane & 7) == 1) atomicAdd(&g_den[t1 * HEADS + (lane >> 3)], ex1);
}

// out = (agg / den) @ wo^T + bo. FFMA2 + LDS.128, 64 nodes per block.
// smem stride 68 floats (272B = 17*16 -> 16B-aligned rows).
#define OUT_NB 64
#define OS_STRIDE 68
__global__ void __launch_bounds__(128) out_kernel(const float* __restrict__ bo,
                                                  float* __restrict__ out)
{
    __shared__ __align__(16) float xs[OUT_F * OS_STRIDE];
    const int t = threadIdx.x;
    const int base = blockIdx.x * OUT_NB;

    // stage normalized agg transposed: xs[f*68 + n] = agg[base+n][f] / den
    for (int k = 0; k < 16; k++) {
        int i = t + k * 128;                 // 0..2047
        int n = i >> 5, c = i & 31;
        int node = base + n; if (node >= N_NODES) node = N_NODES - 1;
        float den = g_den[node * HEADS + (c >> 3)];
        float r = den > 0.f ? __frcp_rn(den) : 0.f;
        float4 gx = ((const float4*)(g_agg + (size_t)node * OUT_F))[c];
        xs[(4 * c + 0) * OS_STRIDE + n] = gx.x * r;
        xs[(4 * c + 1) * OS_STRIDE + n] = gx.y * r;
        xs[(4 * c + 2) * OS_STRIDE + n] = gx.z * r;
        xs[(4 * c + 3) * OS_STRIDE + n] = gx.w * r;
    }
    __syncthreads();

    unsigned long long acc[32];
    const unsigned long long b2 = dup2(bo[t]);
#pragma unroll
    for (int j = 0; j < 32; j++) acc[j] = b2;

#pragma unroll 2
    for (int f = 0; f < OUT_F; f++) {
        const unsigned long long w2 = dup2(g_wot[f * OUT_F + t]);
        const ulonglong2* xp = (const ulonglong2*)(xs + f * OS_STRIDE);
#pragma unroll
        for (int j2 = 0; j2 < 16; j2++) {
            ulonglong2 xq = xp[j2];          // nodes 4j2 .. 4j2+3 (broadcast LDS.128)
            acc[2*j2]   = ffma2(xq.x, w2, acc[2*j2]);
            acc[2*j2+1] = ffma2(xq.y, w2, acc[2*j2+1]);
        }
    }

#pragma unroll
    for (int j = 0; j < 32; j++) {
        int n0 = base + 2 * j;
        if (n0 < N_NODES)     out[(size_t)n0 * OUT_F + t]       = lo2(acc[j]);
        if (n0 + 1 < N_NODES) out[(size_t)(n0 + 1) * OUT_F + t] = hi2(acc[j]);
    }
}

// ---------------- launch ----------------
extern "C" void kernel_launch(void* const* d_in, const int* in_sizes, int n_in,
                              void* d_out, int out_size)
{
    const float* x  = (const float*)d_in[0];
    const int*   ei = (const int*)d_in[1];
    const float* wq = (const float*)d_in[2];
    const float* bq = (const float*)d_in[3];
    const float* wk = (const float*)d_in[4];
    const float* bk = (const float*)d_in[5];
    const float* wv = (const float*)d_in[6];
    const float* bv = (const float*)d_in[7];
    const float* wo = (const float*)d_in[8];
    const float* bo = (const float*)d_in[9];
    float* out = (float*)d_out;

    prep_kernel<<<6250, 256>>>(wo);
    proj_kernel<<<(N_NODES + PROJ_NB - 1) / PROJ_NB, 128>>>(x, wq, bq, wk, bk, wv, bv);
    edge_kernel<<<(N_EDGES / 2 + 7) / 8, 256>>>(ei);   // 2 edges per warp
    out_kernel<<<(N_NODES + OUT_NB - 1) / OUT_NB, 128>>>(bo, out);
}

// round 6
// speedup vs baseline: 1.2291x; 1.2291x over previous
#include <cuda_runtime.h>
#include <cstdint>

#define N_NODES 50000
#define N_EDGES 800000
#define IN_F 128
#define OUT_F 128
#define HEADS 4
#define HEAD_DIM 32

// ---------------- scratch (device globals; no allocation allowed) ----------------
__device__ float g_q[N_NODES * IN_F];
__device__ float g_k[N_NODES * IN_F];
__device__ float g_v[N_NODES * IN_F];
__device__ float g_den[N_NODES * HEADS];    // segment sum of exp(score)
__device__ float g_agg[N_NODES * OUT_F];    // UNNORMALIZED sum of exp(s)*v
__device__ float g_wot[OUT_F * OUT_F];      // wo transposed

// packed fp32x2 FMA (Blackwell FFMA2 — only reachable via PTX fma.rn.f32x2)
__device__ __forceinline__ unsigned long long ffma2(unsigned long long a,
                                                    unsigned long long b,
                                                    unsigned long long c) {
    unsigned long long d;
    asm("fma.rn.f32x2 %0, %1, %2, %3;" : "=l"(d) : "l"(a), "l"(b), "l"(c));
    return d;
}
__device__ __forceinline__ unsigned long long dup2(float w) {
    unsigned long long d;
    asm("mov.b64 %0, {%1, %1};" : "=l"(d) : "r"(__float_as_uint(w)));
    return d;
}
__device__ __forceinline__ float lo2(unsigned long long p) {
    unsigned int a, b;
    asm("mov.b64 {%0, %1}, %2;" : "=r"(a), "=r"(b) : "l"(p));
    return __uint_as_float(a);
}
__device__ __forceinline__ float hi2(unsigned long long p) {
    unsigned int a, b;
    asm("mov.b64 {%0, %1}, %2;" : "=r"(a), "=r"(b) : "l"(p));
    return __uint_as_float(b);
}

// ---------------- kernels ----------------

// zero agg/den + transpose wo (merged prep)
__global__ void prep_kernel(const float* __restrict__ wo) {
    int idx = blockIdx.x * blockDim.x + threadIdx.x;
    if (idx < N_NODES * OUT_F / 4)
        ((float4*)g_agg)[idx] = make_float4(0.f, 0.f, 0.f, 0.f);
    if (idx < N_NODES * HEADS)
        g_den[idx] = 0.f;
    if (idx < OUT_F * OUT_F) {
        int o = idx >> 7, f = idx & 127;
        g_wot[f * OUT_F + o] = wo[idx];
    }
}

// q,k,v projections with node-pair-packed FFMA2 (round-4 version: LDS.64,
// 1 x-pair load feeds 3 FFMA2 for q/k/v -> already fma-bound).
#define PROJ_NB 32
#define XS_STRIDE 34
__global__ void __launch_bounds__(128) proj_kernel(
    const float* __restrict__ x,
    const float* __restrict__ wq, const float* __restrict__ bq,
    const float* __restrict__ wk, const float* __restrict__ bk,
    const float* __restrict__ wv, const float* __restrict__ bv)
{
    __shared__ float xs[IN_F * XS_STRIDE];
    const int t = threadIdx.x;
    const int base = blockIdx.x * PROJ_NB;

    // stage x transposed: xs[f*34 + n] = x[base+n][f]
    for (int k = 0; k < 8; k++) {
        int i = t + k * 128;                 // 0..1023
        int n = i >> 5, c = i & 31;
        int node = base + n; if (node >= N_NODES) node = N_NODES - 1;
        float4 gx = ((const float4*)(x + (size_t)node * IN_F))[c];
        xs[(4 * c + 0) * XS_STRIDE + n] = gx.x;
        xs[(4 * c + 1) * XS_STRIDE + n] = gx.y;
        xs[(4 * c + 2) * XS_STRIDE + n] = gx.z;
        xs[(4 * c + 3) * XS_STRIDE + n] = gx.w;
    }
    __syncthreads();

    const int h = t >> 5, d = t & 31;
    const float* wqp = wq + h * IN_F * HEAD_DIM + d;
    const float* wkp = wk + h * IN_F * HEAD_DIM + d;
    const float* wvp = wv + h * IN_F * HEAD_DIM + d;

    unsigned long long aq[16], ak[16], av[16];
    const unsigned long long bq2 = dup2(bq[h * HEAD_DIM + d]);
    const unsigned long long bk2 = dup2(bk[h * HEAD_DIM + d]);
    const unsigned long long bv2 = dup2(bv[h * HEAD_DIM + d]);
#pragma unroll
    for (int j = 0; j < 16; j++) { aq[j] = bq2; ak[j] = bk2; av[j] = bv2; }

#pragma unroll 2
    for (int f = 0; f < IN_F; f++) {
        const unsigned long long wq2 = dup2(wqp[f * HEAD_DIM]);
        const unsigned long long wk2 = dup2(wkp[f * HEAD_DIM]);
        const unsigned long long wv2 = dup2(wvp[f * HEAD_DIM]);
        const unsigned long long* xp =
            (const unsigned long long*)(xs + f * XS_STRIDE);
#pragma unroll
        for (int j = 0; j < 16; j++) {
            unsigned long long xpair = xp[j];    // nodes 2j, 2j+1 (broadcast LDS.64)
            aq[j] = ffma2(xpair, wq2, aq[j]);
            ak[j] = ffma2(xpair, wk2, ak[j]);
            av[j] = ffma2(xpair, wv2, av[j]);
        }
    }

#pragma unroll
    for (int j = 0; j < 16; j++) {
        int n0 = base + 2 * j;
        if (n0 < N_NODES) {
            size_t r = (size_t)n0 * IN_F;
            g_q[r + t] = lo2(aq[j]); g_k[r + t] = lo2(ak[j]); g_v[r + t] = lo2(av[j]);
        }
        if (n0 + 1 < N_NODES) {
            size_t r = (size_t)(n0 + 1) * IN_F;
            g_q[r + t] = hi2(aq[j]); g_k[r + t] = hi2(ak[j]); g_v[r + t] = hi2(av[j]);
        }
    }
}

// FUSED edge pass, 2 edges per warp for MLP.
__global__ void __launch_bounds__(256) edge_kernel(const int* __restrict__ ei) {
    const int w = (blockIdx.x * blockDim.x + threadIdx.x) >> 5;
    const int lane = threadIdx.x & 31;
    const int e0 = w * 2;
    if (e0 >= N_EDGES) return;
    const int e1 = e0 + 1;

    const int s0 = __ldg(&ei[e0]),           s1 = __ldg(&ei[e1]);
    const int t0 = __ldg(&ei[N_EDGES + e0]), t1 = __ldg(&ei[N_EDGES + e1]);

    const float4 a0 = ((const float4*)(g_q + (size_t)t0 * IN_F))[lane];
    const float4 b0 = ((const float4*)(g_k + (size_t)s0 * IN_F))[lane];
    const float4 a1 = ((const float4*)(g_q + (size_t)t1 * IN_F))[lane];
    const float4 b1 = ((const float4*)(g_k + (size_t)s1 * IN_F))[lane];

    float p0 = a0.x * b0.x + a0.y * b0.y + a0.z * b0.z + a0.w * b0.w;
    float p1 = a1.x * b1.x + a1.y * b1.y + a1.z * b1.z + a1.w * b1.w;

    p0 += __shfl_xor_sync(0xffffffffu, p0, 4);
    p1 += __shfl_xor_sync(0xffffffffu, p1, 4);
    p0 += __shfl_xor_sync(0xffffffffu, p0, 2);
    p1 += __shfl_xor_sync(0xffffffffu, p1, 2);
    p0 += __shfl_xor_sync(0xffffffffu, p0, 1);
    p1 += __shfl_xor_sync(0xffffffffu, p1, 1);

    const float ex0 = __expf(p0);
    const float ex1 = __expf(p1);

    const float4 v0 = ((const float4*)(g_v + (size_t)s0 * IN_F))[lane];
    const float4 v1 = ((const float4*)(g_v + (size_t)s1 * IN_F))[lane];

    float* d0 = g_agg + (size_t)t0 * OUT_F + lane * 4;
    float* d1 = g_agg + (size_t)t1 * OUT_F + lane * 4;
    asm volatile("red.global.add.v4.f32 [%0], {%1, %2, %3, %4};"
                 :: "l"(d0), "f"(ex0 * v0.x), "f"(ex0 * v0.y),
                    "f"(ex0 * v0.z), "f"(ex0 * v0.w) : "memory");
    asm volatile("red.global.add.v4.f32 [%0], {%1, %2, %3, %4};"
                 :: "l"(d1), "f"(ex1 * v1.x), "f"(ex1 * v1.y),
                    "f"(ex1 * v1.z), "f"(ex1 * v1.w) : "memory");

    if ((lane & 7) == 0) atomicAdd(&g_den[t0 * HEADS + (lane >> 3)], ex0);
    if ((lane & 7) == 1) atomicAdd(&g_den[t1 * HEADS + (lane >> 3)], ex1);
}

// out = (agg / den) @ wo^T + bo.
// 2 columns per thread (cslot, cslot+64) share each x-pair LDS.64 -> LDS:FFMA2 = 1:2.
// 32 nodes per block; thread handles 8 node-pairs (mgroup selects which half).
// accs = 16 ull = 32 regs (low pressure; round-4's occupancy preserved).
#define OUT_NB 32
#define OS_STRIDE 34
__global__ void __launch_bounds__(128) out_kernel(const float* __restrict__ bo,
                                                  float* __restrict__ out)
{
    __shared__ float xs[OUT_F * OS_STRIDE];
    const int t = threadIdx.x;
    const int base = blockIdx.x * OUT_NB;

    // stage normalized agg transposed: xs[f*34 + n] = agg[base+n][f] / den
    for (int k = 0; k < 8; k++) {
        int i = t + k * 128;                 // 0..1023
        int n = i >> 5, c = i & 31;
        int node = base + n; if (node >= N_NODES) node = N_NODES - 1;
        float den = g_den[node * HEADS + (c >> 3)];
        float r = den > 0.f ? __frcp_rn(den) : 0.f;
        float4 gx = ((const float4*)(g_agg + (size_t)node * OUT_F))[c];
        xs[(4 * c + 0) * OS_STRIDE + n] = gx.x * r;
        xs[(4 * c + 1) * OS_STRIDE + n] = gx.y * r;
        xs[(4 * c + 2) * OS_STRIDE + n] = gx.z * r;
        xs[(4 * c + 3) * OS_STRIDE + n] = gx.w * r;
    }
    __syncthreads();

    const int cslot = t & 63;                // columns cslot and cslot+64
    const int mg = t >> 6;                   // node-pair half: pairs [mg*8, mg*8+8)

    unsigned long long a0[8], a1[8];
    const unsigned long long b0 = dup2(bo[cslot]);
    const unsigned long long b1 = dup2(bo[cslot + 64]);
#pragma unroll
    for (int j = 0; j < 8; j++) { a0[j] = b0; a1[j] = b1; }

#pragma unroll 2
    for (int f = 0; f < OUT_F; f++) {
        const unsigned long long w0 = dup2(g_wot[f * OUT_F + cslot]);
        const unsigned long long w1 = dup2(g_wot[f * OUT_F + cslot + 64]);
        const unsigned long long* xp =
            (const unsigned long long*)(xs + f * OS_STRIDE) + mg * 8;
#pragma unroll
        for (int j = 0; j < 8; j++) {
            unsigned long long xpair = xp[j];   // broadcast LDS.64, reused for 2 cols
            a0[j] = ffma2(xpair, w0, a0[j]);
            a1[j] = ffma2(xpair, w1, a1[j]);
        }
    }

#pragma unroll
    for (int j = 0; j < 8; j++) {
        int n0 = base + mg * 16 + 2 * j;
        if (n0 < N_NODES) {
            size_t r = (size_t)n0 * OUT_F;
            out[r + cslot]      = lo2(a0[j]);
            out[r + cslot + 64] = lo2(a1[j]);
        }
        if (n0 + 1 < N_NODES) {
            size_t r = (size_t)(n0 + 1) * OUT_F;
            out[r + cslot]      = hi2(a0[j]);
            out[r + cslot + 64] = hi2(a1[j]);
        }
    }
}

// ---------------- launch ----------------
extern "C" void kernel_launch(void* const* d_in, const int* in_sizes, int n_in,
                              void* d_out, int out_size)
{
    const float* x  = (const float*)d_in[0];
    const int*   ei = (const int*)d_in[1];
    const float* wq = (const float*)d_in[2];
    const float* bq = (const float*)d_in[3];
    const float* wk = (const float*)d_in[4];
    const float* bk = (const float*)d_in[5];
    const float* wv = (const float*)d_in[6];
    const float* bv = (const float*)d_in[7];
    const float* wo = (const float*)d_in[8];
    const float* bo = (const float*)d_in[9];
    float* out = (float*)d_out;

    prep_kernel<<<6250, 256>>>(wo);
    proj_kernel<<<(N_NODES + PROJ_NB - 1) / PROJ_NB, 128>>>(x, wq, bq, wk, bk, wv, bv);
    edge_kernel<<<(N_EDGES / 2 + 7) / 8, 256>>>(ei);   // 2 edges per warp
    out_kernel<<<(N_NODES + OUT_NB - 1) / OUT_NB, 128>>>(bo, out);
}

// round 7
// speedup vs baseline: 1.3090x; 1.0651x over previous
#include <cuda_runtime.h>
#include <cuda_fp16.h>
#include <cstdint>

#define N_NODES 50000
#define N_EDGES 800000
#define IN_F 128
#define OUT_F 128
#define HEADS 4
#define HEAD_DIM 32

// ---------------- scratch (device globals; no allocation allowed) ----------------
__device__ __half g_q[N_NODES * IN_F];      // fp16: consumed only by edge gather
__device__ __half g_k[N_NODES * IN_F];
__device__ __half g_v[N_NODES * IN_F];
__device__ float  g_den[N_NODES * HEADS];   // segment sum of exp(score), fp32
__device__ float  g_agg[N_NODES * OUT_F];   // UNNORMALIZED sum of exp(s)*v, fp32
__device__ float  g_wot[OUT_F * OUT_F];     // wo transposed

// packed fp32x2 FMA (Blackwell FFMA2 — only reachable via PTX fma.rn.f32x2)
__device__ __forceinline__ unsigned long long ffma2(unsigned long long a,
                                                    unsigned long long b,
                                                    unsigned long long c) {
    unsigned long long d;
    asm("fma.rn.f32x2 %0, %1, %2, %3;" : "=l"(d) : "l"(a), "l"(b), "l"(c));
    return d;
}
__device__ __forceinline__ unsigned long long dup2(float w) {
    unsigned long long d;
    asm("mov.b64 %0, {%1, %1};" : "=l"(d) : "r"(__float_as_uint(w)));
    return d;
}
__device__ __forceinline__ float lo2(unsigned long long p) {
    unsigned int a, b;
    asm("mov.b64 {%0, %1}, %2;" : "=r"(a), "=r"(b) : "l"(p));
    return __uint_as_float(a);
}
__device__ __forceinline__ float hi2(unsigned long long p) {
    unsigned int a, b;
    asm("mov.b64 {%0, %1}, %2;" : "=r"(a), "=r"(b) : "l"(p));
    return __uint_as_float(b);
}

// ---------------- kernels ----------------

// zero agg/den + transpose wo (merged prep)
__global__ void prep_kernel(const float* __restrict__ wo) {
    int idx = blockIdx.x * blockDim.x + threadIdx.x;
    if (idx < N_NODES * OUT_F / 4)
        ((float4*)g_agg)[idx] = make_float4(0.f, 0.f, 0.f, 0.f);
    if (idx < N_NODES * HEADS)
        g_den[idx] = 0.f;
    if (idx < OUT_F * OUT_F) {
        int o = idx >> 7, f = idx & 127;
        g_wot[f * OUT_F + o] = wo[idx];
    }
}

// q,k,v projections with node-pair-packed FFMA2 (fp32 math, fp16 stores).
#define PROJ_NB 32
#define XS_STRIDE 34
__global__ void __launch_bounds__(128) proj_kernel(
    const float* __restrict__ x,
    const float* __restrict__ wq, const float* __restrict__ bq,
    const float* __restrict__ wk, const float* __restrict__ bk,
    const float* __restrict__ wv, const float* __restrict__ bv)
{
    __shared__ float xs[IN_F * XS_STRIDE];
    const int t = threadIdx.x;
    const int base = blockIdx.x * PROJ_NB;

    // stage x transposed: xs[f*34 + n] = x[base+n][f]
    for (int k = 0; k < 8; k++) {
        int i = t + k * 128;                 // 0..1023
        int n = i >> 5, c = i & 31;
        int node = base + n; if (node >= N_NODES) node = N_NODES - 1;
        float4 gx = ((const float4*)(x + (size_t)node * IN_F))[c];
        xs[(4 * c + 0) * XS_STRIDE + n] = gx.x;
        xs[(4 * c + 1) * XS_STRIDE + n] = gx.y;
        xs[(4 * c + 2) * XS_STRIDE + n] = gx.z;
        xs[(4 * c + 3) * XS_STRIDE + n] = gx.w;
    }
    __syncthreads();

    const int h = t >> 5, d = t & 31;
    const float* wqp = wq + h * IN_F * HEAD_DIM + d;
    const float* wkp = wk + h * IN_F * HEAD_DIM + d;
    const float* wvp = wv + h * IN_F * HEAD_DIM + d;

    unsigned long long aq[16], ak[16], av[16];
    const unsigned long long bq2 = dup2(bq[h * HEAD_DIM + d]);
    const unsigned long long bk2 = dup2(bk[h * HEAD_DIM + d]);
    const unsigned long long bv2 = dup2(bv[h * HEAD_DIM + d]);
#pragma unroll
    for (int j = 0; j < 16; j++) { aq[j] = bq2; ak[j] = bk2; av[j] = bv2; }

#pragma unroll 2
    for (int f = 0; f < IN_F; f++) {
        const unsigned long long wq2 = dup2(wqp[f * HEAD_DIM]);
        const unsigned long long wk2 = dup2(wkp[f * HEAD_DIM]);
        const unsigned long long wv2 = dup2(wvp[f * HEAD_DIM]);
        const unsigned long long* xp =
            (const unsigned long long*)(xs + f * XS_STRIDE);
#pragma unroll
        for (int j = 0; j < 16; j++) {
            unsigned long long xpair = xp[j];    // nodes 2j, 2j+1 (broadcast LDS.64)
            aq[j] = ffma2(xpair, wq2, aq[j]);
            ak[j] = ffma2(xpair, wk2, ak[j]);
            av[j] = ffma2(xpair, wv2, av[j]);
        }
    }

#pragma unroll
    for (int j = 0; j < 16; j++) {
        int n0 = base + 2 * j;
        if (n0 < N_NODES) {
            size_t r = (size_t)n0 * IN_F;
            g_q[r + t] = __float2half_rn(lo2(aq[j]));
            g_k[r + t] = __float2half_rn(lo2(ak[j]));
            g_v[r + t] = __float2half_rn(lo2(av[j]));
        }
        if (n0 + 1 < N_NODES) {
            size_t r = (size_t)(n0 + 1) * IN_F;
            g_q[r + t] = __float2half_rn(hi2(aq[j]));
            g_k[r + t] = __float2half_rn(hi2(ak[j]));
            g_v[r + t] = __float2half_rn(hi2(av[j]));
        }
    }
}

// FUSED edge pass, 2 edges per warp. fp16 gathers (half traffic), fp32 math/agg.
// Lane covers dims 4l..4l+3 (uint2 = 4 halves); head = lane>>3.
__global__ void __launch_bounds__(256) edge_kernel(const int* __restrict__ ei) {
    const int w = (blockIdx.x * blockDim.x + threadIdx.x) >> 5;
    const int lane = threadIdx.x & 31;
    const int e0 = w * 2;
    if (e0 >= N_EDGES) return;
    const int e1 = e0 + 1;

    const int s0 = __ldg(&ei[e0]),           s1 = __ldg(&ei[e1]);
    const int t0 = __ldg(&ei[N_EDGES + e0]), t1 = __ldg(&ei[N_EDGES + e1]);

    const uint2 qa0 = ((const uint2*)(g_q + (size_t)t0 * IN_F))[lane];
    const uint2 ka0 = ((const uint2*)(g_k + (size_t)s0 * IN_F))[lane];
    const uint2 qa1 = ((const uint2*)(g_q + (size_t)t1 * IN_F))[lane];
    const uint2 ka1 = ((const uint2*)(g_k + (size_t)s1 * IN_F))[lane];

    float2 qx0 = __half22float2(*(const __half2*)&qa0.x);
    float2 qy0 = __half22float2(*(const __half2*)&qa0.y);
    float2 kx0 = __half22float2(*(const __half2*)&ka0.x);
    float2 ky0 = __half22float2(*(const __half2*)&ka0.y);
    float2 qx1 = __half22float2(*(const __half2*)&qa1.x);
    float2 qy1 = __half22float2(*(const __half2*)&qa1.y);
    float2 kx1 = __half22float2(*(const __half2*)&ka1.x);
    float2 ky1 = __half22float2(*(const __half2*)&ka1.y);

    float p0 = qx0.x * kx0.x + qx0.y * kx0.y + qy0.x * ky0.x + qy0.y * ky0.y;
    float p1 = qx1.x * kx1.x + qx1.y * kx1.y + qy1.x * ky1.x + qy1.y * ky1.y;

    p0 += __shfl_xor_sync(0xffffffffu, p0, 4);
    p1 += __shfl_xor_sync(0xffffffffu, p1, 4);
    p0 += __shfl_xor_sync(0xffffffffu, p0, 2);
    p1 += __shfl_xor_sync(0xffffffffu, p1, 2);
    p0 += __shfl_xor_sync(0xffffffffu, p0, 1);
    p1 += __shfl_xor_sync(0xffffffffu, p1, 1);

    const float ex0 = __expf(p0);
    const float ex1 = __expf(p1);

    const uint2 va0 = ((const uint2*)(g_v + (size_t)s0 * IN_F))[lane];
    const uint2 va1 = ((const uint2*)(g_v + (size_t)s1 * IN_F))[lane];
    float2 vx0 = __half22float2(*(const __half2*)&va0.x);
    float2 vy0 = __half22float2(*(const __half2*)&va0.y);
    float2 vx1 = __half22float2(*(const __half2*)&va1.x);
    float2 vy1 = __half22float2(*(const __half2*)&va1.y);

    float* d0 = g_agg + (size_t)t0 * OUT_F + lane * 4;
    float* d1 = g_agg + (size_t)t1 * OUT_F + lane * 4;
    asm volatile("red.global.add.v4.f32 [%0], {%1, %2, %3, %4};"
                 :: "l"(d0), "f"(ex0 * vx0.x), "f"(ex0 * vx0.y),
                    "f"(ex0 * vy0.x), "f"(ex0 * vy0.y) : "memory");
    asm volatile("red.global.add.v4.f32 [%0], {%1, %2, %3, %4};"
                 :: "l"(d1), "f"(ex1 * vx1.x), "f"(ex1 * vx1.y),
                    "f"(ex1 * vy1.x), "f"(ex1 * vy1.y) : "memory");

    if ((lane & 7) == 0) atomicAdd(&g_den[t0 * HEADS + (lane >> 3)], ex0);
    if ((lane & 7) == 1) atomicAdd(&g_den[t1 * HEADS + (lane >> 3)], ex1);
}

// out = (agg / den) @ wo^T + bo.
// 2 columns per thread share each x load; xs reads vectorized to LDS.128.
// 32 nodes/block, 16 ull accs (R6 register budget preserved).
#define OUT_NB 32
#define OS_STRIDE 36
__global__ void __launch_bounds__(128) out_kernel(const float* __restrict__ bo,
                                                  float* __restrict__ out)
{
    __shared__ __align__(16) float xs[OUT_F * OS_STRIDE];
    const int t = threadIdx.x;
    const int base = blockIdx.x * OUT_NB;

    // stage normalized agg transposed: xs[f*36 + n] = agg[base+n][f] / den
    for (int k = 0; k < 8; k++) {
        int i = t + k * 128;                 // 0..1023
        int n = i >> 5, c = i & 31;
        int node = base + n; if (node >= N_NODES) node = N_NODES - 1;
        float den = g_den[node * HEADS + (c >> 3)];
        float r = den > 0.f ? __frcp_rn(den) : 0.f;
        float4 gx = ((const float4*)(g_agg + (size_t)node * OUT_F))[c];
        xs[(4 * c + 0) * OS_STRIDE + n] = gx.x * r;
        xs[(4 * c + 1) * OS_STRIDE + n] = gx.y * r;
        xs[(4 * c + 2) * OS_STRIDE + n] = gx.z * r;
        xs[(4 * c + 3) * OS_STRIDE + n] = gx.w * r;
    }
    __syncthreads();

    const int cslot = t & 63;                // columns cslot and cslot+64
    const int mg = t >> 6;                   // node-pair half: pairs [mg*8, mg*8+8)

    unsigned long long a0[8], a1[8];
    const unsigned long long b0 = dup2(bo[cslot]);
    const unsigned long long b1 = dup2(bo[cslot + 64]);
#pragma unroll
    for (int j = 0; j < 8; j++) { a0[j] = b0; a1[j] = b1; }

#pragma unroll 2
    for (int f = 0; f < OUT_F; f++) {
        const unsigned long long w0 = dup2(g_wot[f * OUT_F + cslot]);
        const unsigned long long w1 = dup2(g_wot[f * OUT_F + cslot + 64]);
        const ulonglong2* xp =
            (const ulonglong2*)(xs + f * OS_STRIDE) + mg * 4;
#pragma unroll
        for (int j2 = 0; j2 < 4; j2++) {
            ulonglong2 xq = xp[j2];          // 2 node-pairs per LDS.128 (broadcast)
            a0[2*j2]   = ffma2(xq.x, w0, a0[2*j2]);
            a1[2*j2]   = ffma2(xq.x, w1, a1[2*j2]);
            a0[2*j2+1] = ffma2(xq.y, w0, a0[2*j2+1]);
            a1[2*j2+1] = ffma2(xq.y, w1, a1[2*j2+1]);
        }
    }

#pragma unroll
    for (int j = 0; j < 8; j++) {
        int n0 = base + mg * 16 + 2 * j;
        if (n0 < N_NODES) {
            size_t r = (size_t)n0 * OUT_F;
            out[r + cslot]      = lo2(a0[j]);
            out[r + cslot + 64] = lo2(a1[j]);
        }
        if (n0 + 1 < N_NODES) {
            size_t r = (size_t)(n0 + 1) * OUT_F;
            out[r + cslot]      = hi2(a0[j]);
            out[r + cslot + 64] = hi2(a1[j]);
        }
    }
}

// ---------------- launch ----------------
extern "C" void kernel_launch(void* const* d_in, const int* in_sizes, int n_in,
                              void* d_out, int out_size)
{
    const float* x  = (const float*)d_in[0];
    const int*   ei = (const int*)d_in[1];
    const float* wq = (const float*)d_in[2];
    const float* bq = (const float*)d_in[3];
    const float* wk = (const float*)d_in[4];
    const float* bk = (const float*)d_in[5];
    const float* wv = (const float*)d_in[6];
    const float* bv = (const float*)d_in[7];
    const float* wo = (const float*)d_in[8];
    const float* bo = (const float*)d_in[9];
    float* out = (float*)d_out;

    prep_kernel<<<6250, 256>>>(wo);
    proj_kernel<<<(N_NODES + PROJ_NB - 1) / PROJ_NB, 128>>>(x, wq, bq, wk, bk, wv, bv);
    edge_kernel<<<(N_EDGES / 2 + 7) / 8, 256>>>(ei);   // 2 edges per warp
    out_kernel<<<(N_NODES + OUT_NB - 1) / OUT_NB, 128>>>(bo, out);
}